// round 4
// baseline (speedup 1.0000x reference)
#include <cuda_runtime.h>

#define FULL_MASK 0xFFFFFFFFu

__device__ __forceinline__ unsigned long long mk_evict_last_policy() {
    unsigned long long pol;
    asm volatile("createpolicy.fractional.L2::evict_last.b64 %0, 1.0;" : "=l"(pol));
    return pol;
}

__device__ __forceinline__ float4 ldg_feat4(const float4* p, unsigned long long pol) {
    float4 v;
    asm volatile("ld.global.nc.L2::cache_hint.v4.f32 {%0,%1,%2,%3}, [%4], %5;"
                 : "=f"(v.x), "=f"(v.y), "=f"(v.z), "=f"(v.w) : "l"(p), "l"(pol));
    return v;
}

// Problem constants
// B=8, H=256, W=256, K=8, C=64, N=B*H*W=524288
// R_NDC = 1.5/256*2 = 3/256; R_NDC^2 = 9/65536 (exact in binary)
__global__ __launch_bounds__(256, 3) void rast_blend_kernel(
    const float* __restrict__ dist,
    const float* __restrict__ zbuf,
    const int*   __restrict__ pidx,
    const float* __restrict__ feat,
    float*       __restrict__ out)
{
    constexpr int C = 64;
    constexpr int K = 8;
    constexpr float INV_R2 = 65536.0f / 9.0f;

    __shared__ float s[C * 33];   // [channel][pixel-in-tile], pad 33 for readout

    const int tid = threadIdx.x;
    const int wp  = tid >> 5;       // warp id 0..7
    const int l   = tid & 31;       // lane
    const int hl  = l >> 4;         // half-warp: 0 handles even k, 1 handles odd k
    const int l16 = l & 15;         // lane within half-warp -> channels 4*l16..4*l16+3

    const int tileBase = blockIdx.x * 32;     // first pixel (linear over B*H*W)
    const int warpPix  = tileBase + wp * 4;   // this warp: 4 consecutive pixels

    // ---- header: 4 pixels x K=8 = 32 contiguous entries, one coalesced load each ----
    const long hdr = (long)warpPix * K + l;
    float d  = __ldcs(dist + hdr);
    float z  = __ldcs(zbuf + hdr);
    int   id = __ldcs(pidx + hdr);

    float a = 1.0f - sqrtf(fminf(fmaxf(d * INV_R2, 0.001f), 1.0f));
    bool valid = (z >= 0.0f) && (id >= 0);
    a  = valid ? a : 0.0f;
    id = (id < 0) ? 0 : id;       // safe gather index (weight already zeroed)

    const float4* __restrict__ f4p = reinterpret_cast<const float4*>(feat);
    const unsigned long long pol = mk_evict_last_policy();

    #pragma unroll
    for (int p = 0; p < 4; ++p) {
        // every lane builds the full weight vector w[0..7] (front-to-back compositing)
        float w[K];
        float T = 1.0f;
        #pragma unroll
        for (int k = 0; k < K; ++k) {
            float ak = __shfl_sync(FULL_MASK, a, p * 8 + k);
            w[k] = ak * T;
            T *= (1.0f - ak);
        }

        // paired-row gathers: one LDG.128 covers TWO 256B feature rows
        // (lanes 0-15 -> row id[2j], lanes 16-31 -> row id[2j+1])
        float4 acc = make_float4(0.f, 0.f, 0.f, 0.f);
        #pragma unroll
        for (int j = 0; j < 4; ++j) {
            int   ik = __shfl_sync(FULL_MASK, id, p * 8 + 2 * j + hl);
            float wk = hl ? w[2 * j + 1] : w[2 * j];
            float4 f = ldg_feat4(f4p + (long)ik * 16 + l16, pol);
            acc.x = fmaf(wk, f.x, acc.x);
            acc.y = fmaf(wk, f.y, acc.y);
            acc.z = fmaf(wk, f.z, acc.z);
            acc.w = fmaf(wk, f.w, acc.w);
        }

        // merge even-k / odd-k partials across half-warps
        acc.x += __shfl_xor_sync(FULL_MASK, acc.x, 16);
        acc.y += __shfl_xor_sync(FULL_MASK, acc.y, 16);
        acc.z += __shfl_xor_sync(FULL_MASK, acc.z, 16);
        acc.w += __shfl_xor_sync(FULL_MASK, acc.w, 16);

        if (hl == 0) {
            const int col = wp * 4 + p;
            const int c0  = 4 * l16;
            s[(c0 + 0) * 33 + col] = acc.x;
            s[(c0 + 1) * 33 + col] = acc.y;
            s[(c0 + 2) * 33 + col] = acc.z;
            s[(c0 + 3) * 33 + col] = acc.w;
        }
    }
    __syncthreads();

    // ---- coalesced transposed writeout: out[b][c][h][w0..w0+31] ----
    const int b  = tileBase >> 16;        // / (H*W)
    const int hw = tileBase & 65535;
    const int h  = hw >> 8;
    const int w0 = hw & 255;              // multiple of 32
    float* obase = out + ((long)b * C) * 65536 + (long)h * 256 + w0;

    #pragma unroll
    for (int it = 0; it < 8; ++it) {
        const int c = it * 8 + wp;
        __stcs(obase + (long)c * 65536 + l, s[c * 33 + l]);
    }
}

extern "C" void kernel_launch(void* const* d_in, const int* in_sizes, int n_in,
                              void* d_out, int out_size) {
    const float* dist = (const float*)d_in[0];
    const float* zbuf = (const float*)d_in[1];
    const int*   pidx = (const int*)d_in[2];
    const float* feat = (const float*)d_in[3];
    float* out = (float*)d_out;

    const int nPix = 8 * 256 * 256;       // 524288
    rast_blend_kernel<<<nPix / 32, 256>>>(dist, zbuf, pidx, feat, out);
}